// round 4
// baseline (speedup 1.0000x reference)
#include <cuda_runtime.h>

#define MDIM  256
#define NHEAD 8
#define HDIM  32
#define SEQ   128
#define BATCH 2
#define P     (BATCH*SEQ*SEQ)   // 32768 positions
#define QKV_N (3*MDIM)          // 768

// ---------------- scratch (device globals; no cudaMalloc allowed) -----------
__device__ float g_qkv[(size_t)P * QKV_N];   // 100.7 MB
__device__ float g_mean[P];
__device__ float g_rstd[P];
__device__ float g_o[(size_t)P * MDIM];      // 33.6 MB
__device__ int   g_mask_is_u8;

// ---------------- mask dtype detector ---------------------------------------
// Reads the first 8192 int32 words = 32768 bytes, which is in-bounds whether
// the mask buffer holds 32768 int32 (131072 B) or 32768 uint8 (32768 B).
// int32 bools -> every word is 0 or 1. packed uint8 bools -> words with high
// bytes set appear w.p. ~1. Deterministic.
__global__ void detect_mask_kernel(const int* __restrict__ m) {
    __shared__ int flag;
    if (threadIdx.x == 0) flag = 0;
    __syncthreads();
    for (int i = threadIdx.x; i < P / 4; i += 256) {
        int v = m[i];
        if (v != 0 && v != 1) flag = 1;   // benign race: all writers store 1
    }
    __syncthreads();
    if (threadIdx.x == 0) g_mask_is_u8 = flag;
}

// ---------------- LayerNorm statistics: one warp per 256-wide row -----------
__global__ void ln_stats_kernel(const float* __restrict__ x,
                                float* __restrict__ mean,
                                float* __restrict__ rstd) {
    int row = blockIdx.x * blockDim.y + threadIdx.y;
    const float* xr = x + (size_t)row * MDIM;
    float s = 0.f, s2 = 0.f;
    for (int i = threadIdx.x; i < MDIM; i += 32) {
        float v = xr[i];
        s += v; s2 += v * v;
    }
    #pragma unroll
    for (int o = 16; o; o >>= 1) {
        s  += __shfl_xor_sync(0xffffffffu, s, o);
        s2 += __shfl_xor_sync(0xffffffffu, s2, o);
    }
    if (threadIdx.x == 0) {
        float m   = s * (1.f / MDIM);
        float var = fmaxf(s2 * (1.f / MDIM) - m * m, 0.f);
        mean[row] = m;
        rstd[row] = rsqrtf(var + 1e-5f);
    }
}

// ---------------- tiled fp32 GEMM: C[m,n] = sum_k A[m,k]*B[n,k] -------------
// Optionally applies LayerNorm to A rows on load (fused for the QKV proj).
#define BM  128
#define BN  64
#define BKK 16

template<bool LN>
__global__ __launch_bounds__(256) void gemm_kernel(
    const float* __restrict__ A, const float* __restrict__ Bmat,
    float* __restrict__ C, int M, int N, int K,
    const float* __restrict__ mean, const float* __restrict__ rstd,
    const float* __restrict__ gamma, const float* __restrict__ beta)
{
    __shared__ float As[BKK][BM];
    __shared__ float Bs[BKK][BN];

    const int tid = threadIdx.x;
    const int bm  = blockIdx.x * BM;
    const int bn  = blockIdx.y * BN;
    const int tx  = tid & 15;        // n micro-tile (4 cols)
    const int ty  = tid >> 4;        // m micro-tile (8 rows)
    const int ar  = tid >> 2;        // 0..63
    const int ac  = (tid & 3) << 2;  // 0,4,8,12

    float acc[8][4] = {};

    float mu0 = 0.f, rs0 = 0.f, mu1 = 0.f, rs1 = 0.f;
    if (LN) {
        mu0 = mean[bm + ar];      rs0 = rstd[bm + ar];
        mu1 = mean[bm + ar + 64]; rs1 = rstd[bm + ar + 64];
    }
    const float* Arow0 = A + (size_t)(bm + ar) * K;
    const float* Arow1 = A + (size_t)(bm + ar + 64) * K;
    const float* Brow  = Bmat + (size_t)(bn + ar) * K;

    for (int k0 = 0; k0 < K; k0 += BKK) {
        float4 a0 = *(const float4*)(Arow0 + k0 + ac);
        float4 a1 = *(const float4*)(Arow1 + k0 + ac);
        float4 bv = *(const float4*)(Brow  + k0 + ac);
        if (LN) {
            float4 g  = *(const float4*)(gamma + k0 + ac);
            float4 be = *(const float4*)(beta  + k0 + ac);
            a0.x = (a0.x - mu0) * rs0 * g.x + be.x;
            a0.y = (a0.y - mu0) * rs0 * g.y + be.y;
            a0.z = (a0.z - mu0) * rs0 * g.z + be.z;
            a0.w = (a0.w - mu0) * rs0 * g.w + be.w;
            a1.x = (a1.x - mu1) * rs1 * g.x + be.x;
            a1.y = (a1.y - mu1) * rs1 * g.y + be.y;
            a1.z = (a1.z - mu1) * rs1 * g.z + be.z;
            a1.w = (a1.w - mu1) * rs1 * g.w + be.w;
        }
        As[ac + 0][ar]      = a0.x;
        As[ac + 1][ar]      = a0.y;
        As[ac + 2][ar]      = a0.z;
        As[ac + 3][ar]      = a0.w;
        As[ac + 0][ar + 64] = a1.x;
        As[ac + 1][ar + 64] = a1.y;
        As[ac + 2][ar + 64] = a1.z;
        As[ac + 3][ar + 64] = a1.w;
        Bs[ac + 0][ar] = bv.x;
        Bs[ac + 1][ar] = bv.y;
        Bs[ac + 2][ar] = bv.z;
        Bs[ac + 3][ar] = bv.w;
        __syncthreads();

        #pragma unroll
        for (int kk = 0; kk < BKK; kk++) {
            float4 av0 = *(const float4*)&As[kk][ty * 8];
            float4 av1 = *(const float4*)&As[kk][ty * 8 + 4];
            float4 bb  = *(const float4*)&Bs[kk][tx * 4];
            float av[8] = {av0.x, av0.y, av0.z, av0.w, av1.x, av1.y, av1.z, av1.w};
            float bw[4] = {bb.x, bb.y, bb.z, bb.w};
            #pragma unroll
            for (int i = 0; i < 8; i++)
                #pragma unroll
                for (int j = 0; j < 4; j++)
                    acc[i][j] = fmaf(av[i], bw[j], acc[i][j]);
        }
        __syncthreads();
    }

    #pragma unroll
    for (int i = 0; i < 8; i++) {
        float4 r = make_float4(acc[i][0], acc[i][1], acc[i][2], acc[i][3]);
        *(float4*)&C[(size_t)(bm + ty * 8 + i) * N + bn + tx * 4] = r;
    }
}

// ---------------- axial rotary on q,k (first 32 channels only) --------------
__global__ void rotary_kernel(float* __restrict__ qkv) {
    int gid = blockIdx.x * blockDim.x + threadIdx.x;
    if (gid >= P * 16) return;
    int i = gid & 15;          // pair index 0..15
    int p = gid >> 4;          // position
    int y = p & 127;
    int x = (p >> 7) & 127;
    int j = (i < 8) ? i : (i - 8);
    // inv_freq[j] = 10000^(-(2j)/16)
    float invf = expf(-(2.f * (float)j / 16.f) * logf(10000.f));
    float t = (i < 8) ? (-1.f + 2.f * (float)x / 127.f)
                      : (-1.f + 2.f * (float)y / 127.f);
    float th = t * invf;
    float c = cosf(th), sn = sinf(th);

    float* q = qkv + (size_t)p * QKV_N + 2 * i;
    float q0 = q[0], q1 = q[1];
    q[0] = q0 * c - q1 * sn;
    q[1] = q1 * c + q0 * sn;
    float* k = q + MDIM;
    float k0 = k[0], k1 = k[1];
    k[0] = k0 * c - k1 * sn;
    k[1] = k1 * c + k0 * sn;
}

// ---------------- attention: one block per (b, x, h), 128 thr (1/query) ----
__global__ __launch_bounds__(128) void attn_kernel(
    const float* __restrict__ qkv,
    const unsigned char* __restrict__ mask8,
    const int* __restrict__ mask32,
    float* __restrict__ o)
{
    __shared__ float4 Ks4[SEQ][8];
    __shared__ float4 Vs4[SEQ][8];
    __shared__ unsigned char msk[SEQ];

    int blk = blockIdx.x;
    int h = blk & 7;
    int x = (blk >> 3) & 127;
    int b = blk >> 10;
    int tid = threadIdx.x;
    int rowbase = (b * SEQ + x) * SEQ;

    for (int fi = tid; fi < SEQ * 8; fi += 128) {
        int row = fi >> 3, d4 = fi & 7;
        const float* base = qkv + (size_t)(rowbase + row) * QKV_N + h * HDIM + d4 * 4;
        Ks4[row][d4] = *(const float4*)(base + MDIM);
        Vs4[row][d4] = *(const float4*)(base + 2 * MDIM);
    }
    {
        size_t midx = (size_t)(b * SEQ + x) * SEQ + tid;
        msk[tid] = g_mask_is_u8 ? mask8[midx] : (unsigned char)mask32[midx];
    }

    const float scale = 0.17677669529663687f;  // 32^-0.5 (folded into q)
    float4 q[8];
    const float4* qp = (const float4*)(qkv + (size_t)(rowbase + tid) * QKV_N + h * HDIM);
    #pragma unroll
    for (int j = 0; j < 8; j++) {
        float4 v = qp[j];
        v.x *= scale; v.y *= scale; v.z *= scale; v.w *= scale;
        q[j] = v;
    }
    __syncthreads();

    // pass 1: running max + normalizer
    float m = -3.0e38f, l = 0.f;
    for (int k = 0; k < SEQ; k++) {
        float s = 0.f;
        #pragma unroll
        for (int j = 0; j < 8; j++) {
            float4 kv = Ks4[k][j];
            s = fmaf(q[j].x, kv.x, s); s = fmaf(q[j].y, kv.y, s);
            s = fmaf(q[j].z, kv.z, s); s = fmaf(q[j].w, kv.w, s);
        }
        if (msk[k]) s = -1e9f;
        float mn = fmaxf(m, s);
        l = l * __expf(m - mn) + __expf(s - mn);
        m = mn;
    }

    // pass 2: recompute scores, accumulate P@V
    float4 acc[8];
    #pragma unroll
    for (int j = 0; j < 8; j++) acc[j] = make_float4(0.f, 0.f, 0.f, 0.f);
    for (int k = 0; k < SEQ; k++) {
        float s = 0.f;
        #pragma unroll
        for (int j = 0; j < 8; j++) {
            float4 kv = Ks4[k][j];
            s = fmaf(q[j].x, kv.x, s); s = fmaf(q[j].y, kv.y, s);
            s = fmaf(q[j].z, kv.z, s); s = fmaf(q[j].w, kv.w, s);
        }
        if (msk[k]) s = -1e9f;
        float p = __expf(s - m);
        #pragma unroll
        for (int j = 0; j < 8; j++) {
            float4 v = Vs4[k][j];
            acc[j].x = fmaf(p, v.x, acc[j].x);
            acc[j].y = fmaf(p, v.y, acc[j].y);
            acc[j].z = fmaf(p, v.z, acc[j].z);
            acc[j].w = fmaf(p, v.w, acc[j].w);
        }
    }
    float inv = 1.f / l;
    float4* op = (float4*)(o + (size_t)(rowbase + tid) * MDIM + h * HDIM);
    #pragma unroll
    for (int j = 0; j < 8; j++) {
        acc[j].x *= inv; acc[j].y *= inv; acc[j].z *= inv; acc[j].w *= inv;
        op[j] = acc[j];
    }
}

// ---------------- launch ----------------------------------------------------
extern "C" void kernel_launch(void* const* d_in, const int* in_sizes, int n_in,
                              void* d_out, int out_size) {
    // Identify inputs by element count (robust to ordering).
    const float* pair_act = nullptr;
    const void*  pair_mask = nullptr;
    const float* ln_gamma = nullptr;
    const float* ln_beta  = nullptr;
    const float* Wqkv = nullptr;
    const float* Wout = nullptr;
    for (int i = 0; i < n_in; i++) {
        int sz = in_sizes[i];
        if      (sz == P * MDIM)  pair_act  = (const float*)d_in[i];
        else if (sz == P)         pair_mask = d_in[i];
        else if (sz == QKV_N * MDIM) Wqkv   = (const float*)d_in[i];
        else if (sz == MDIM * MDIM)  Wout   = (const float*)d_in[i];
        else if (sz == MDIM) {
            if (!ln_gamma) ln_gamma = (const float*)d_in[i];
            else           ln_beta  = (const float*)d_in[i];
        }
    }
    float* out = (float*)d_out;

    float *qkv, *meanp, *rstdp, *op;
    cudaGetSymbolAddress((void**)&qkv,   g_qkv);
    cudaGetSymbolAddress((void**)&meanp, g_mean);
    cudaGetSymbolAddress((void**)&rstdp, g_rstd);
    cudaGetSymbolAddress((void**)&op,    g_o);

    detect_mask_kernel<<<1, 256>>>((const int*)pair_mask);

    ln_stats_kernel<<<P / 8, dim3(32, 8)>>>(pair_act, meanp, rstdp);

    gemm_kernel<true><<<dim3(P / BM, QKV_N / BN), 256>>>(
        pair_act, Wqkv, qkv, P, QKV_N, MDIM, meanp, rstdp, ln_gamma, ln_beta);

    rotary_kernel<<<(P * 16) / 256, 256>>>(qkv);

    attn_kernel<<<BATCH * SEQ * NHEAD, 128>>>(
        qkv, (const unsigned char*)pair_mask, (const int*)pair_mask, op);

    gemm_kernel<false><<<dim3(P / BM, MDIM / BN), 256>>>(
        op, Wout, out, P, MDIM, MDIM, nullptr, nullptr, nullptr, nullptr);
}